// round 1
// baseline (speedup 1.0000x reference)
#include <cuda_runtime.h>
#include <math.h>

#define Bmax  8
#define Hh    128
#define Ww    128
#define Tt    (Hh*Ww)       // 16384
#define Cc    192
#define C4    (Cc/4)        // 48
#define HIDD  768
#define MTILE 32

// ---------------- scratch (static device arrays; no allocs) ----------------
__device__ float4 g_xx[(size_t)Bmax * Tt * C4];   // OmniShift output, [B,T,C] as float4
__device__ float  g_eff[Cc * 25];                 // folded 5x5 depthwise weights
__device__ float  g_wvp[Cc * HIDD];               // g[h] * Wv[c,h]
__device__ float  g_G[Cc];                        // sum_h g[h]*Wv[c,h]
__device__ float  g_Bc[Cc];                       // sum_h b[h]*Wv[c,h]

// ---------------- prep kernels ----------------
__global__ void prep_eff(const float* __restrict__ w1, const float* __restrict__ w3,
                         const float* __restrict__ w5, const float* __restrict__ alpha) {
    int c = threadIdx.x;   // 192 threads
    float a0 = alpha[0], a1 = alpha[1], a2 = alpha[2], a3 = alpha[3];
    for (int t = 0; t < 25; t++) {
        int di = t / 5, dj = t % 5;
        float v = a3 * w5[c * 25 + t];
        if (di >= 1 && di <= 3 && dj >= 1 && dj <= 3)
            v += a2 * w3[c * 9 + (di - 1) * 3 + (dj - 1)];
        if (di == 2 && dj == 2)
            v += a1 * w1[c] + a0;
        g_eff[c * 25 + t] = v;
    }
}

__global__ void prep_wv(const float* __restrict__ Wv, const float* __restrict__ g) {
    int i = blockIdx.x * 256 + threadIdx.x;
    if (i < Cc * HIDD) g_wvp[i] = g[i % HIDD] * Wv[i];
}

__global__ void prep_gb(const float* __restrict__ Wv, const float* __restrict__ g,
                        const float* __restrict__ bb) {
    int c = threadIdx.x;   // 192 threads
    float sg = 0.f, sb = 0.f;
    for (int h = 0; h < HIDD; h++) {
        float w = Wv[(size_t)c * HIDD + h];
        sg += g[h] * w;
        sb += bb[h] * w;
    }
    g_G[c] = sg;
    g_Bc[c] = sb;
}

// ---------------- OmniShift conv kernel ----------------
// grid: (Ww/32, Hh, B); block: 192 threads = 48 c4-groups x 4 w-segments of 8
__global__ void __launch_bounds__(192) conv_k(const float* __restrict__ x) {
    __shared__ float4 s_eff[25][48];
    int tid = threadIdx.x;
    for (int i = tid; i < 25 * 48; i += 192) {
        int tap = i / 48, c4 = i % 48;
        int c = c4 * 4;
        s_eff[tap][c4] = make_float4(g_eff[(c + 0) * 25 + tap], g_eff[(c + 1) * 25 + tap],
                                     g_eff[(c + 2) * 25 + tap], g_eff[(c + 3) * 25 + tap]);
    }
    __syncthreads();

    int c4 = tid % 48;
    int wseg = tid / 48;                    // 0..3
    int w0 = (blockIdx.x * 4 + wseg) * 8;   // 8 outputs along w
    int h = blockIdx.y;
    size_t bbase = (size_t)blockIdx.z * Tt * C4;
    const float4* xb = ((const float4*)x) + bbase;

    float4 acc[8];
#pragma unroll
    for (int k = 0; k < 8; k++) acc[k] = make_float4(0.f, 0.f, 0.f, 0.f);

#pragma unroll
    for (int di = -2; di <= 2; di++) {
        int hh = h + di;
        float4 row[12];
        if (hh >= 0 && hh < Hh) {
            const float4* xr = xb + (size_t)hh * Ww * C4 + c4;
#pragma unroll
            for (int j = 0; j < 12; j++) {
                int w = w0 - 2 + j;
                row[j] = (w >= 0 && w < Ww) ? xr[(size_t)w * C4]
                                            : make_float4(0.f, 0.f, 0.f, 0.f);
            }
        } else {
#pragma unroll
            for (int j = 0; j < 12; j++) row[j] = make_float4(0.f, 0.f, 0.f, 0.f);
        }
#pragma unroll
        for (int dj = 0; dj < 5; dj++) {
            float4 wg = s_eff[(di + 2) * 5 + dj][c4];
#pragma unroll
            for (int k = 0; k < 8; k++) {
                acc[k].x = fmaf(row[k + dj].x, wg.x, acc[k].x);
                acc[k].y = fmaf(row[k + dj].y, wg.y, acc[k].y);
                acc[k].z = fmaf(row[k + dj].z, wg.z, acc[k].z);
                acc[k].w = fmaf(row[k + dj].w, wg.w, acc[k].w);
            }
        }
    }

    float4* xxb = g_xx + bbase + (size_t)h * Ww * C4 + c4;
#pragma unroll
    for (int k = 0; k < 8; k++) xxb[(size_t)(w0 + k) * C4] = acc[k];
}

// ---------------- fused main kernel ----------------
__device__ __forceinline__ void fma4(float& acc, float4 a, float4 b) {
    acc = fmaf(a.x, b.x, acc);
    acc = fmaf(a.y, b.y, acc);
    acc = fmaf(a.z, b.z, acc);
    acc = fmaf(a.w, b.w, acc);
}

// smem layout sizes (floats)
#define SXK_OFF  0
#define SXR_OFF  (MTILE * 196)
#define SW_OFF   (SXR_OFF + MTILE * 196)
#define SW_SZ    25344                      // max(128*196, 192*132)
#define SK_OFF   (SW_OFF + SW_SZ)
#define SG_OFF   (SK_OFF + MTILE * 132)
#define SB_OFF   (SG_OFF + Cc)
#define SS1_OFF  (SB_OFF + Cc)
#define SS2_OFF  (SS1_OFF + 256)
#define SMU_OFF  (SS2_OFF + 256)
#define SSG_OFF  (SMU_OFF + MTILE)
#define SMEM_FLOATS (SSG_OFF + MTILE)
#define SMEM_BYTES (SMEM_FLOATS * 4)

__global__ void __launch_bounds__(256, 1) fused(
    const float* __restrict__ x, const float* __restrict__ mixk,
    const float* __restrict__ mixr, const float* __restrict__ Wk,
    const float* __restrict__ Wr, float* __restrict__ out)
{
    extern __shared__ float sm[];
    float* s_xk = sm + SXK_OFF;
    float* s_xr = sm + SXR_OFF;
    float* s_w  = sm + SW_OFF;
    float* s_k  = sm + SK_OFF;
    float* s_G  = sm + SG_OFF;
    float* s_B  = sm + SB_OFF;
    float* s_s1 = sm + SS1_OFF;
    float* s_s2 = sm + SS2_OFF;
    float* s_mu = sm + SMU_OFF;
    float* s_sg = sm + SSG_OFF;

    int tid = threadIdx.x;
    size_t m0 = (size_t)blockIdx.x * MTILE;

    // Phase 1: load x rows + xx rows, form xk / xr into smem
    for (int i = tid; i < MTILE * C4; i += 256) {
        int m = i / C4, c4 = i % C4;
        float4 xv  = ((const float4*)x)[(m0 + m) * C4 + c4];
        float4 xxv = g_xx[(m0 + m) * C4 + c4];
        float4 mk  = ((const float4*)mixk)[c4];
        float4 mr  = ((const float4*)mixr)[c4];
        float4 vk, vr;
        vk.x = xv.x * mk.x + xxv.x * (1.f - mk.x);
        vk.y = xv.y * mk.y + xxv.y * (1.f - mk.y);
        vk.z = xv.z * mk.z + xxv.z * (1.f - mk.z);
        vk.w = xv.w * mk.w + xxv.w * (1.f - mk.w);
        vr.x = xv.x * mr.x + xxv.x * (1.f - mr.x);
        vr.y = xv.y * mr.y + xxv.y * (1.f - mr.y);
        vr.z = xv.z * mr.z + xxv.z * (1.f - mr.z);
        vr.w = xv.w * mr.w + xxv.w * (1.f - mr.w);
        *((float4*)(s_xk + m * 196 + c4 * 4)) = vk;
        *((float4*)(s_xr + m * 196 + c4 * 4)) = vr;
    }
    for (int i = tid; i < Cc; i += 256) { s_G[i] = g_G[i]; s_B[i] = g_Bc[i]; }

    const int gm = tid >> 5;   // 0..7
    const int gn = tid & 31;   // 0..31

    float accA[4][6];
#pragma unroll
    for (int i = 0; i < 4; i++)
#pragma unroll
        for (int j = 0; j < 6; j++) accA[i][j] = 0.f;
    float rs = 0.f, rs2 = 0.f;

    // ---- HID tile loop: GEMM1 (relu^2) -> stats -> GEMM2 accumulate ----
    for (int ht = 0; ht < 6; ht++) {
        int h0 = ht * 128;
        __syncthreads();
        // stage Wk tile [128][192], row stride 196
        for (int i = tid; i < 128 * C4; i += 256) {
            int hh = i / C4, c4 = i % C4;
            *((float4*)(s_w + hh * 196 + c4 * 4)) =
                ((const float4*)(Wk + (size_t)(h0 + hh) * Cc))[c4];
        }
        __syncthreads();

        float acc1[4][4];
#pragma unroll
        for (int i = 0; i < 4; i++)
#pragma unroll
            for (int j = 0; j < 4; j++) acc1[i][j] = 0.f;

#pragma unroll 2
        for (int c4 = 0; c4 < C4; c4++) {
            float4 av[4], bv[4];
#pragma unroll
            for (int i = 0; i < 4; i++)
                av[i] = *((const float4*)(s_xk + (gm * 4 + i) * 196 + c4 * 4));
#pragma unroll
            for (int j = 0; j < 4; j++)
                bv[j] = *((const float4*)(s_w + (gn + 32 * j) * 196 + c4 * 4));
#pragma unroll
            for (int i = 0; i < 4; i++)
#pragma unroll
                for (int j = 0; j < 4; j++) fma4(acc1[i][j], av[i], bv[j]);
        }
        __syncthreads();   // done reading s_w (Wk) and prior s_k fully consumed

        // write relu^2 into s_k (row stride 132)
#pragma unroll
        for (int i = 0; i < 4; i++)
#pragma unroll
            for (int j = 0; j < 4; j++) {
                float v = fmaxf(acc1[i][j], 0.f);
                s_k[(gm * 4 + i) * 132 + gn + 32 * j] = v * v;
            }
        // stage Wv' tile [192][128], row stride 132
        for (int i = tid; i < Cc * 32; i += 256) {
            int c = i / 32, h4 = i % 32;
            *((float4*)(s_w + c * 132 + h4 * 4)) =
                ((const float4*)(g_wvp + (size_t)c * HIDD + h0))[h4];
        }
        __syncthreads();

        // running row stats on raw k
        {
            int row = gn;
            for (int hh = gm; hh < 128; hh += 8) {
                float v = s_k[row * 132 + hh];
                rs += v;
                rs2 += v * v;
            }
        }

        // GEMM2: A[m][c] += k_tile @ Wv'^T
#pragma unroll 2
        for (int h4 = 0; h4 < 32; h4++) {
            float4 av[4], bv[6];
#pragma unroll
            for (int i = 0; i < 4; i++)
                av[i] = *((const float4*)(s_k + (gm * 4 + i) * 132 + h4 * 4));
#pragma unroll
            for (int j = 0; j < 6; j++)
                bv[j] = *((const float4*)(s_w + (gn + 32 * j) * 132 + h4 * 4));
#pragma unroll
            for (int i = 0; i < 4; i++)
#pragma unroll
                for (int j = 0; j < 6; j++) fma4(accA[i][j], av[i], bv[j]);
        }
    }

    // reduce per-row stats across the 8 partial threads per row
    s_s1[tid] = rs;
    s_s2[tid] = rs2;
    __syncthreads();
    if (tid < MTILE) {
        float a = 0.f, b2 = 0.f;
        for (int l = 0; l < 8; l++) { a += s_s1[tid + 32 * l]; b2 += s_s2[tid + 32 * l]; }
        float mu = a * (1.f / HIDD);
        float var = b2 * (1.f / HIDD) - mu * mu;
        s_mu[tid] = mu;
        s_sg[tid] = rsqrtf(var + 1e-5f);
    }

    // ---- GEMM3: r = xr @ Wr^T (two 96-row halves staged in s_w) ----
    float acc3[4][6];
#pragma unroll
    for (int i = 0; i < 4; i++)
#pragma unroll
        for (int j = 0; j < 6; j++) acc3[i][j] = 0.f;

    for (int half = 0; half < 2; half++) {
        __syncthreads();
        for (int i = tid; i < 96 * C4; i += 256) {
            int dd = i / C4, c4 = i % C4;
            *((float4*)(s_w + dd * 196 + c4 * 4)) =
                ((const float4*)(Wr + (size_t)(half * 96 + dd) * Cc))[c4];
        }
        __syncthreads();
#pragma unroll 2
        for (int c4 = 0; c4 < C4; c4++) {
            float4 av[4], bv[3];
#pragma unroll
            for (int i = 0; i < 4; i++)
                av[i] = *((const float4*)(s_xr + (gm * 4 + i) * 196 + c4 * 4));
#pragma unroll
            for (int jj = 0; jj < 3; jj++)
                bv[jj] = *((const float4*)(s_w + (gn + 32 * jj) * 196 + c4 * 4));
#pragma unroll
            for (int i = 0; i < 4; i++)
#pragma unroll
                for (int jj = 0; jj < 3; jj++) fma4(acc3[i][3 * half + jj], av[i], bv[jj]);
        }
    }

    // ---- epilogue: kv = s*(A - mu*G) + Bc ; out = sigmoid(r) * kv ----
#pragma unroll
    for (int i = 0; i < 4; i++) {
        int m = gm * 4 + i;
        float mu = s_mu[m], sg = s_sg[m];
#pragma unroll
        for (int j = 0; j < 6; j++) {
            int c = gn + 32 * j;
            float kv = sg * (accA[i][j] - mu * s_G[c]) + s_B[c];
            float r = 1.f / (1.f + expf(-acc3[i][j]));
            out[(m0 + m) * Cc + c] = r * kv;
        }
    }
}

// ---------------- host launcher ----------------
extern "C" void kernel_launch(void* const* d_in, const int* in_sizes, int n_in,
                              void* d_out, int out_size) {
    const float* x     = (const float*)d_in[0];
    const float* w1    = (const float*)d_in[1];
    const float* w3    = (const float*)d_in[2];
    const float* w5    = (const float*)d_in[3];
    const float* alpha = (const float*)d_in[4];
    const float* mixk  = (const float*)d_in[5];
    const float* mixr  = (const float*)d_in[6];
    const float* Wk    = (const float*)d_in[7];
    const float* ln_g  = (const float*)d_in[8];
    const float* ln_b  = (const float*)d_in[9];
    const float* Wr    = (const float*)d_in[10];
    const float* Wv    = (const float*)d_in[11];
    float* out = (float*)d_out;

    int nrow = in_sizes[0] / Cc;     // B*T
    int Bv = nrow / Tt;              // batch

    prep_eff<<<1, 192>>>(w1, w3, w5, alpha);
    prep_wv<<<(Cc * HIDD + 255) / 256, 256>>>(Wv, ln_g);
    prep_gb<<<1, 192>>>(Wv, ln_g, ln_b);
    conv_k<<<dim3(Ww / 32, Hh, Bv), 192>>>(x);

    cudaFuncSetAttribute(fused, cudaFuncAttributeMaxDynamicSharedMemorySize, SMEM_BYTES);
    fused<<<nrow / MTILE, 256, SMEM_BYTES>>>(x, mixk, mixr, Wk, Wr, out);
}

// round 2
// speedup vs baseline: 1.0006x; 1.0006x over previous
#include <cuda_runtime.h>
#include <math.h>

#define Bmax  8
#define Hh    128
#define Ww    128
#define Tt    (Hh*Ww)       // 16384
#define Cc    192
#define C4    (Cc/4)        // 48
#define HIDD  768
#define MTILE 32

// ---------------- scratch (static device arrays; no allocs) ----------------
__device__ float4 g_xx[(size_t)Bmax * Tt * C4];   // OmniShift output, [B,T,C] as float4
__device__ float  g_eff[Cc * 25];                 // folded 5x5 depthwise weights
__device__ float  g_wvp[Cc * HIDD];               // g[h] * Wv[c,h]
__device__ float  g_G[Cc];                        // sum_h g[h]*Wv[c,h]
__device__ float  g_Bc[Cc];                       // sum_h b[h]*Wv[c,h]

// ---------------- prep kernels ----------------
__global__ void prep_eff(const float* __restrict__ w1, const float* __restrict__ w3,
                         const float* __restrict__ w5, const float* __restrict__ alpha) {
    int c = threadIdx.x;   // 192 threads
    float a0 = alpha[0], a1 = alpha[1], a2 = alpha[2], a3 = alpha[3];
    for (int t = 0; t < 25; t++) {
        int di = t / 5, dj = t % 5;
        float v = a3 * w5[c * 25 + t];
        if (di >= 1 && di <= 3 && dj >= 1 && dj <= 3)
            v += a2 * w3[c * 9 + (di - 1) * 3 + (dj - 1)];
        if (di == 2 && dj == 2)
            v += a1 * w1[c] + a0;
        g_eff[c * 25 + t] = v;
    }
}

__global__ void prep_wv(const float* __restrict__ Wv, const float* __restrict__ g) {
    int i = blockIdx.x * 256 + threadIdx.x;
    if (i < Cc * HIDD) g_wvp[i] = g[i % HIDD] * Wv[i];
}

__global__ void prep_gb(const float* __restrict__ Wv, const float* __restrict__ g,
                        const float* __restrict__ bb) {
    int c = threadIdx.x;   // 192 threads
    float sg = 0.f, sb = 0.f;
    for (int h = 0; h < HIDD; h++) {
        float w = Wv[(size_t)c * HIDD + h];
        sg += g[h] * w;
        sb += bb[h] * w;
    }
    g_G[c] = sg;
    g_Bc[c] = sb;
}

// ---------------- OmniShift conv kernel ----------------
// grid: (Ww/32, Hh, B); block: 192 threads = 48 c4-groups x 4 w-segments of 8
__global__ void __launch_bounds__(192) conv_k(const float* __restrict__ x) {
    __shared__ float4 s_eff[25][48];
    int tid = threadIdx.x;
    for (int i = tid; i < 25 * 48; i += 192) {
        int tap = i / 48, c4 = i % 48;
        int c = c4 * 4;
        s_eff[tap][c4] = make_float4(g_eff[(c + 0) * 25 + tap], g_eff[(c + 1) * 25 + tap],
                                     g_eff[(c + 2) * 25 + tap], g_eff[(c + 3) * 25 + tap]);
    }
    __syncthreads();

    int c4 = tid % 48;
    int wseg = tid / 48;                    // 0..3
    int w0 = (blockIdx.x * 4 + wseg) * 8;   // 8 outputs along w
    int h = blockIdx.y;
    size_t bbase = (size_t)blockIdx.z * Tt * C4;
    const float4* xb = ((const float4*)x) + bbase;

    float4 acc[8];
#pragma unroll
    for (int k = 0; k < 8; k++) acc[k] = make_float4(0.f, 0.f, 0.f, 0.f);

#pragma unroll
    for (int di = -2; di <= 2; di++) {
        int hh = h + di;
        float4 row[12];
        if (hh >= 0 && hh < Hh) {
            const float4* xr = xb + (size_t)hh * Ww * C4 + c4;
#pragma unroll
            for (int j = 0; j < 12; j++) {
                int w = w0 - 2 + j;
                row[j] = (w >= 0 && w < Ww) ? xr[(size_t)w * C4]
                                            : make_float4(0.f, 0.f, 0.f, 0.f);
            }
        } else {
#pragma unroll
            for (int j = 0; j < 12; j++) row[j] = make_float4(0.f, 0.f, 0.f, 0.f);
        }
#pragma unroll
        for (int dj = 0; dj < 5; dj++) {
            float4 wg = s_eff[(di + 2) * 5 + dj][c4];
#pragma unroll
            for (int k = 0; k < 8; k++) {
                acc[k].x = fmaf(row[k + dj].x, wg.x, acc[k].x);
                acc[k].y = fmaf(row[k + dj].y, wg.y, acc[k].y);
                acc[k].z = fmaf(row[k + dj].z, wg.z, acc[k].z);
                acc[k].w = fmaf(row[k + dj].w, wg.w, acc[k].w);
            }
        }
    }

    float4* xxb = g_xx + bbase + (size_t)h * Ww * C4 + c4;
#pragma unroll
    for (int k = 0; k < 8; k++) xxb[(size_t)(w0 + k) * C4] = acc[k];
}

// ---------------- fused main kernel ----------------
__device__ __forceinline__ void fma4(float& acc, float4 a, float4 b) {
    acc = fmaf(a.x, b.x, acc);
    acc = fmaf(a.y, b.y, acc);
    acc = fmaf(a.z, b.z, acc);
    acc = fmaf(a.w, b.w, acc);
}

// smem layout sizes (floats)
#define SXK_OFF  0
#define SXR_OFF  (MTILE * 196)
#define SW_OFF   (SXR_OFF + MTILE * 196)
#define SW_SZ    25344                      // max(128*196, 192*132)
#define SK_OFF   (SW_OFF + SW_SZ)
#define SG_OFF   (SK_OFF + MTILE * 132)
#define SB_OFF   (SG_OFF + Cc)
#define SS1_OFF  (SB_OFF + Cc)
#define SS2_OFF  (SS1_OFF + 256)
#define SMU_OFF  (SS2_OFF + 256)
#define SSG_OFF  (SMU_OFF + MTILE)
#define SMEM_FLOATS (SSG_OFF + MTILE)
#define SMEM_BYTES (SMEM_FLOATS * 4)

__global__ void __launch_bounds__(256, 1) fused(
    const float* __restrict__ x, const float* __restrict__ mixk,
    const float* __restrict__ mixr, const float* __restrict__ Wk,
    const float* __restrict__ Wr, float* __restrict__ out)
{
    extern __shared__ float sm[];
    float* s_xk = sm + SXK_OFF;
    float* s_xr = sm + SXR_OFF;
    float* s_w  = sm + SW_OFF;
    float* s_k  = sm + SK_OFF;
    float* s_G  = sm + SG_OFF;
    float* s_B  = sm + SB_OFF;
    float* s_s1 = sm + SS1_OFF;
    float* s_s2 = sm + SS2_OFF;
    float* s_mu = sm + SMU_OFF;
    float* s_sg = sm + SSG_OFF;

    int tid = threadIdx.x;
    size_t m0 = (size_t)blockIdx.x * MTILE;

    // Phase 1: load x rows + xx rows, form xk / xr into smem
    for (int i = tid; i < MTILE * C4; i += 256) {
        int m = i / C4, c4 = i % C4;
        float4 xv  = ((const float4*)x)[(m0 + m) * C4 + c4];
        float4 xxv = g_xx[(m0 + m) * C4 + c4];
        float4 mk  = ((const float4*)mixk)[c4];
        float4 mr  = ((const float4*)mixr)[c4];
        float4 vk, vr;
        vk.x = xv.x * mk.x + xxv.x * (1.f - mk.x);
        vk.y = xv.y * mk.y + xxv.y * (1.f - mk.y);
        vk.z = xv.z * mk.z + xxv.z * (1.f - mk.z);
        vk.w = xv.w * mk.w + xxv.w * (1.f - mk.w);
        vr.x = xv.x * mr.x + xxv.x * (1.f - mr.x);
        vr.y = xv.y * mr.y + xxv.y * (1.f - mr.y);
        vr.z = xv.z * mr.z + xxv.z * (1.f - mr.z);
        vr.w = xv.w * mr.w + xxv.w * (1.f - mr.w);
        *((float4*)(s_xk + m * 196 + c4 * 4)) = vk;
        *((float4*)(s_xr + m * 196 + c4 * 4)) = vr;
    }
    for (int i = tid; i < Cc; i += 256) { s_G[i] = g_G[i]; s_B[i] = g_Bc[i]; }

    const int gm = tid >> 5;   // 0..7
    const int gn = tid & 31;   // 0..31

    float accA[4][6];
#pragma unroll
    for (int i = 0; i < 4; i++)
#pragma unroll
        for (int j = 0; j < 6; j++) accA[i][j] = 0.f;
    float rs = 0.f, rs2 = 0.f;

    // ---- HID tile loop: GEMM1 (relu^2) -> stats -> GEMM2 accumulate ----
    for (int ht = 0; ht < 6; ht++) {
        int h0 = ht * 128;
        __syncthreads();
        // stage Wk tile [128][192], row stride 196
        for (int i = tid; i < 128 * C4; i += 256) {
            int hh = i / C4, c4 = i % C4;
            *((float4*)(s_w + hh * 196 + c4 * 4)) =
                ((const float4*)(Wk + (size_t)(h0 + hh) * Cc))[c4];
        }
        __syncthreads();

        float acc1[4][4];
#pragma unroll
        for (int i = 0; i < 4; i++)
#pragma unroll
            for (int j = 0; j < 4; j++) acc1[i][j] = 0.f;

#pragma unroll 2
        for (int c4 = 0; c4 < C4; c4++) {
            float4 av[4], bv[4];
#pragma unroll
            for (int i = 0; i < 4; i++)
                av[i] = *((const float4*)(s_xk + (gm * 4 + i) * 196 + c4 * 4));
#pragma unroll
            for (int j = 0; j < 4; j++)
                bv[j] = *((const float4*)(s_w + (gn + 32 * j) * 196 + c4 * 4));
#pragma unroll
            for (int i = 0; i < 4; i++)
#pragma unroll
                for (int j = 0; j < 4; j++) fma4(acc1[i][j], av[i], bv[j]);
        }
        __syncthreads();   // done reading s_w (Wk) and prior s_k fully consumed

        // write relu^2 into s_k (row stride 132)
#pragma unroll
        for (int i = 0; i < 4; i++)
#pragma unroll
            for (int j = 0; j < 4; j++) {
                float v = fmaxf(acc1[i][j], 0.f);
                s_k[(gm * 4 + i) * 132 + gn + 32 * j] = v * v;
            }
        // stage Wv' tile [192][128], row stride 132
        for (int i = tid; i < Cc * 32; i += 256) {
            int c = i / 32, h4 = i % 32;
            *((float4*)(s_w + c * 132 + h4 * 4)) =
                ((const float4*)(g_wvp + (size_t)c * HIDD + h0))[h4];
        }
        __syncthreads();

        // running row stats on raw k
        {
            int row = gn;
            for (int hh = gm; hh < 128; hh += 8) {
                float v = s_k[row * 132 + hh];
                rs += v;
                rs2 += v * v;
            }
        }

        // GEMM2: A[m][c] += k_tile @ Wv'^T
#pragma unroll 2
        for (int h4 = 0; h4 < 32; h4++) {
            float4 av[4], bv[6];
#pragma unroll
            for (int i = 0; i < 4; i++)
                av[i] = *((const float4*)(s_k + (gm * 4 + i) * 132 + h4 * 4));
#pragma unroll
            for (int j = 0; j < 6; j++)
                bv[j] = *((const float4*)(s_w + (gn + 32 * j) * 132 + h4 * 4));
#pragma unroll
            for (int i = 0; i < 4; i++)
#pragma unroll
                for (int j = 0; j < 6; j++) fma4(accA[i][j], av[i], bv[j]);
        }
    }

    // reduce per-row stats across the 8 partial threads per row
    s_s1[tid] = rs;
    s_s2[tid] = rs2;
    __syncthreads();
    if (tid < MTILE) {
        float a = 0.f, b2 = 0.f;
        for (int l = 0; l < 8; l++) { a += s_s1[tid + 32 * l]; b2 += s_s2[tid + 32 * l]; }
        float mu = a * (1.f / HIDD);
        float var = b2 * (1.f / HIDD) - mu * mu;
        s_mu[tid] = mu;
        s_sg[tid] = rsqrtf(var + 1e-5f);
    }

    // ---- GEMM3: r = xr @ Wr^T (two 96-row halves staged in s_w) ----
    float acc3[4][6];
#pragma unroll
    for (int i = 0; i < 4; i++)
#pragma unroll
        for (int j = 0; j < 6; j++) acc3[i][j] = 0.f;

    for (int half = 0; half < 2; half++) {
        __syncthreads();
        for (int i = tid; i < 96 * C4; i += 256) {
            int dd = i / C4, c4 = i % C4;
            *((float4*)(s_w + dd * 196 + c4 * 4)) =
                ((const float4*)(Wr + (size_t)(half * 96 + dd) * Cc))[c4];
        }
        __syncthreads();
#pragma unroll 2
        for (int c4 = 0; c4 < C4; c4++) {
            float4 av[4], bv[3];
#pragma unroll
            for (int i = 0; i < 4; i++)
                av[i] = *((const float4*)(s_xr + (gm * 4 + i) * 196 + c4 * 4));
#pragma unroll
            for (int jj = 0; jj < 3; jj++)
                bv[jj] = *((const float4*)(s_w + (gn + 32 * jj) * 196 + c4 * 4));
#pragma unroll
            for (int i = 0; i < 4; i++)
#pragma unroll
                for (int jj = 0; jj < 3; jj++) fma4(acc3[i][3 * half + jj], av[i], bv[jj]);
        }
    }

    // ---- epilogue: kv = s*(A - mu*G) + Bc ; out = sigmoid(r) * kv ----
#pragma unroll
    for (int i = 0; i < 4; i++) {
        int m = gm * 4 + i;
        float mu = s_mu[m], sg = s_sg[m];
#pragma unroll
        for (int j = 0; j < 6; j++) {
            int c = gn + 32 * j;
            float kv = sg * (accA[i][j] - mu * s_G[c]) + s_B[c];
            float r = 1.f / (1.f + expf(-acc3[i][j]));
            out[(m0 + m) * Cc + c] = r * kv;
        }
    }
}

// ---------------- host launcher ----------------
extern "C" void kernel_launch(void* const* d_in, const int* in_sizes, int n_in,
                              void* d_out, int out_size) {
    const float* x     = (const float*)d_in[0];
    const float* w1    = (const float*)d_in[1];
    const float* w3    = (const float*)d_in[2];
    const float* w5    = (const float*)d_in[3];
    const float* alpha = (const float*)d_in[4];
    const float* mixk  = (const float*)d_in[5];
    const float* mixr  = (const float*)d_in[6];
    const float* Wk    = (const float*)d_in[7];
    const float* ln_g  = (const float*)d_in[8];
    const float* ln_b  = (const float*)d_in[9];
    const float* Wr    = (const float*)d_in[10];
    const float* Wv    = (const float*)d_in[11];
    float* out = (float*)d_out;

    int nrow = in_sizes[0] / Cc;     // B*T
    int Bv = nrow / Tt;              // batch

    prep_eff<<<1, 192>>>(w1, w3, w5, alpha);
    prep_wv<<<(Cc * HIDD + 255) / 256, 256>>>(Wv, ln_g);
    prep_gb<<<1, 192>>>(Wv, ln_g, ln_b);
    conv_k<<<dim3(Ww / 32, Hh, Bv), 192>>>(x);

    cudaFuncSetAttribute(fused, cudaFuncAttributeMaxDynamicSharedMemorySize, SMEM_BYTES);
    fused<<<nrow / MTILE, 256, SMEM_BYTES>>>(x, mixk, mixr, Wk, Wr, out);
}

// round 3
// speedup vs baseline: 1.0007x; 1.0001x over previous
#include <cuda_runtime.h>
#include <math.h>

#define Bmax  8
#define Hh    128
#define Ww    128
#define Tt    (Hh*Ww)       // 16384
#define Cc    192
#define C4    (Cc/4)        // 48
#define HIDD  768
#define MTILE 32

// ---------------- scratch (static device arrays; no allocs) ----------------
__device__ float4 g_xx[(size_t)Bmax * Tt * C4];   // OmniShift output, [B,T,C] as float4
__device__ float  g_eff[Cc * 25];                 // folded 5x5 depthwise weights
__device__ float  g_wvp[Cc * HIDD];               // g[h] * Wv[c,h]
__device__ float  g_G[Cc];                        // sum_h g[h]*Wv[c,h]
__device__ float  g_Bc[Cc];                       // sum_h b[h]*Wv[c,h]

// ---------------- prep kernels ----------------
__global__ void prep_eff(const float* __restrict__ w1, const float* __restrict__ w3,
                         const float* __restrict__ w5, const float* __restrict__ alpha) {
    int c = threadIdx.x;   // 192 threads
    float a0 = alpha[0], a1 = alpha[1], a2 = alpha[2], a3 = alpha[3];
    for (int t = 0; t < 25; t++) {
        int di = t / 5, dj = t % 5;
        float v = a3 * w5[c * 25 + t];
        if (di >= 1 && di <= 3 && dj >= 1 && dj <= 3)
            v += a2 * w3[c * 9 + (di - 1) * 3 + (dj - 1)];
        if (di == 2 && dj == 2)
            v += a1 * w1[c] + a0;
        g_eff[c * 25 + t] = v;
    }
}

__global__ void prep_wv(const float* __restrict__ Wv, const float* __restrict__ g) {
    int i = blockIdx.x * 256 + threadIdx.x;
    if (i < Cc * HIDD) g_wvp[i] = g[i % HIDD] * Wv[i];
}

__global__ void prep_gb(const float* __restrict__ Wv, const float* __restrict__ g,
                        const float* __restrict__ bb) {
    int c = threadIdx.x;   // 192 threads
    float sg = 0.f, sb = 0.f;
    for (int h = 0; h < HIDD; h++) {
        float w = Wv[(size_t)c * HIDD + h];
        sg += g[h] * w;
        sb += bb[h] * w;
    }
    g_G[c] = sg;
    g_Bc[c] = sb;
}

// ---------------- OmniShift conv kernel ----------------
// grid: (Ww/32, Hh, B); block: 192 threads = 48 c4-groups x 4 w-segments of 8
__global__ void __launch_bounds__(192) conv_k(const float* __restrict__ x) {
    __shared__ float4 s_eff[25][48];
    int tid = threadIdx.x;
    for (int i = tid; i < 25 * 48; i += 192) {
        int tap = i / 48, c4 = i % 48;
        int c = c4 * 4;
        s_eff[tap][c4] = make_float4(g_eff[(c + 0) * 25 + tap], g_eff[(c + 1) * 25 + tap],
                                     g_eff[(c + 2) * 25 + tap], g_eff[(c + 3) * 25 + tap]);
    }
    __syncthreads();

    int c4 = tid % 48;
    int wseg = tid / 48;                    // 0..3
    int w0 = (blockIdx.x * 4 + wseg) * 8;   // 8 outputs along w
    int h = blockIdx.y;
    size_t bbase = (size_t)blockIdx.z * Tt * C4;
    const float4* xb = ((const float4*)x) + bbase;

    float4 acc[8];
#pragma unroll
    for (int k = 0; k < 8; k++) acc[k] = make_float4(0.f, 0.f, 0.f, 0.f);

#pragma unroll
    for (int di = -2; di <= 2; di++) {
        int hh = h + di;
        float4 row[12];
        if (hh >= 0 && hh < Hh) {
            const float4* xr = xb + (size_t)hh * Ww * C4 + c4;
#pragma unroll
            for (int j = 0; j < 12; j++) {
                int w = w0 - 2 + j;
                row[j] = (w >= 0 && w < Ww) ? xr[(size_t)w * C4]
                                            : make_float4(0.f, 0.f, 0.f, 0.f);
            }
        } else {
#pragma unroll
            for (int j = 0; j < 12; j++) row[j] = make_float4(0.f, 0.f, 0.f, 0.f);
        }
#pragma unroll
        for (int dj = 0; dj < 5; dj++) {
            float4 wg = s_eff[(di + 2) * 5 + dj][c4];
#pragma unroll
            for (int k = 0; k < 8; k++) {
                acc[k].x = fmaf(row[k + dj].x, wg.x, acc[k].x);
                acc[k].y = fmaf(row[k + dj].y, wg.y, acc[k].y);
                acc[k].z = fmaf(row[k + dj].z, wg.z, acc[k].z);
                acc[k].w = fmaf(row[k + dj].w, wg.w, acc[k].w);
            }
        }
    }

    float4* xxb = g_xx + bbase + (size_t)h * Ww * C4 + c4;
#pragma unroll
    for (int k = 0; k < 8; k++) xxb[(size_t)(w0 + k) * C4] = acc[k];
}

// ---------------- fused main kernel ----------------
__device__ __forceinline__ void fma4(float& acc, float4 a, float4 b) {
    acc = fmaf(a.x, b.x, acc);
    acc = fmaf(a.y, b.y, acc);
    acc = fmaf(a.z, b.z, acc);
    acc = fmaf(a.w, b.w, acc);
}

// smem layout sizes (floats)
#define SXK_OFF  0
#define SXR_OFF  (MTILE * 196)
#define SW_OFF   (SXR_OFF + MTILE * 196)
#define SW_SZ    25344                      // max(128*196, 192*132)
#define SK_OFF   (SW_OFF + SW_SZ)
#define SG_OFF   (SK_OFF + MTILE * 132)
#define SB_OFF   (SG_OFF + Cc)
#define SS1_OFF  (SB_OFF + Cc)
#define SS2_OFF  (SS1_OFF + 256)
#define SMU_OFF  (SS2_OFF + 256)
#define SSG_OFF  (SMU_OFF + MTILE)
#define SMEM_FLOATS (SSG_OFF + MTILE)
#define SMEM_BYTES (SMEM_FLOATS * 4)

__global__ void __launch_bounds__(256, 1) fused(
    const float* __restrict__ x, const float* __restrict__ mixk,
    const float* __restrict__ mixr, const float* __restrict__ Wk,
    const float* __restrict__ Wr, float* __restrict__ out)
{
    extern __shared__ float sm[];
    float* s_xk = sm + SXK_OFF;
    float* s_xr = sm + SXR_OFF;
    float* s_w  = sm + SW_OFF;
    float* s_k  = sm + SK_OFF;
    float* s_G  = sm + SG_OFF;
    float* s_B  = sm + SB_OFF;
    float* s_s1 = sm + SS1_OFF;
    float* s_s2 = sm + SS2_OFF;
    float* s_mu = sm + SMU_OFF;
    float* s_sg = sm + SSG_OFF;

    int tid = threadIdx.x;
    size_t m0 = (size_t)blockIdx.x * MTILE;

    // Phase 1: load x rows + xx rows, form xk / xr into smem
    for (int i = tid; i < MTILE * C4; i += 256) {
        int m = i / C4, c4 = i % C4;
        float4 xv  = ((const float4*)x)[(m0 + m) * C4 + c4];
        float4 xxv = g_xx[(m0 + m) * C4 + c4];
        float4 mk  = ((const float4*)mixk)[c4];
        float4 mr  = ((const float4*)mixr)[c4];
        float4 vk, vr;
        vk.x = xv.x * mk.x + xxv.x * (1.f - mk.x);
        vk.y = xv.y * mk.y + xxv.y * (1.f - mk.y);
        vk.z = xv.z * mk.z + xxv.z * (1.f - mk.z);
        vk.w = xv.w * mk.w + xxv.w * (1.f - mk.w);
        vr.x = xv.x * mr.x + xxv.x * (1.f - mr.x);
        vr.y = xv.y * mr.y + xxv.y * (1.f - mr.y);
        vr.z = xv.z * mr.z + xxv.z * (1.f - mr.z);
        vr.w = xv.w * mr.w + xxv.w * (1.f - mr.w);
        *((float4*)(s_xk + m * 196 + c4 * 4)) = vk;
        *((float4*)(s_xr + m * 196 + c4 * 4)) = vr;
    }
    for (int i = tid; i < Cc; i += 256) { s_G[i] = g_G[i]; s_B[i] = g_Bc[i]; }

    const int gm = tid >> 5;   // 0..7
    const int gn = tid & 31;   // 0..31

    float accA[4][6];
#pragma unroll
    for (int i = 0; i < 4; i++)
#pragma unroll
        for (int j = 0; j < 6; j++) accA[i][j] = 0.f;
    float rs = 0.f, rs2 = 0.f;

    // ---- HID tile loop: GEMM1 (relu^2) -> stats -> GEMM2 accumulate ----
    for (int ht = 0; ht < 6; ht++) {
        int h0 = ht * 128;
        __syncthreads();
        // stage Wk tile [128][192], row stride 196
        for (int i = tid; i < 128 * C4; i += 256) {
            int hh = i / C4, c4 = i % C4;
            *((float4*)(s_w + hh * 196 + c4 * 4)) =
                ((const float4*)(Wk + (size_t)(h0 + hh) * Cc))[c4];
        }
        __syncthreads();

        float acc1[4][4];
#pragma unroll
        for (int i = 0; i < 4; i++)
#pragma unroll
            for (int j = 0; j < 4; j++) acc1[i][j] = 0.f;

#pragma unroll 2
        for (int c4 = 0; c4 < C4; c4++) {
            float4 av[4], bv[4];
#pragma unroll
            for (int i = 0; i < 4; i++)
                av[i] = *((const float4*)(s_xk + (gm * 4 + i) * 196 + c4 * 4));
#pragma unroll
            for (int j = 0; j < 4; j++)
                bv[j] = *((const float4*)(s_w + (gn + 32 * j) * 196 + c4 * 4));
#pragma unroll
            for (int i = 0; i < 4; i++)
#pragma unroll
                for (int j = 0; j < 4; j++) fma4(acc1[i][j], av[i], bv[j]);
        }
        __syncthreads();   // done reading s_w (Wk) and prior s_k fully consumed

        // write relu^2 into s_k (row stride 132)
#pragma unroll
        for (int i = 0; i < 4; i++)
#pragma unroll
            for (int j = 0; j < 4; j++) {
                float v = fmaxf(acc1[i][j], 0.f);
                s_k[(gm * 4 + i) * 132 + gn + 32 * j] = v * v;
            }
        // stage Wv' tile [192][128], row stride 132
        for (int i = tid; i < Cc * 32; i += 256) {
            int c = i / 32, h4 = i % 32;
            *((float4*)(s_w + c * 132 + h4 * 4)) =
                ((const float4*)(g_wvp + (size_t)c * HIDD + h0))[h4];
        }
        __syncthreads();

        // running row stats on raw k
        {
            int row = gn;
            for (int hh = gm; hh < 128; hh += 8) {
                float v = s_k[row * 132 + hh];
                rs += v;
                rs2 += v * v;
            }
        }

        // GEMM2: A[m][c] += k_tile @ Wv'^T
#pragma unroll 2
        for (int h4 = 0; h4 < 32; h4++) {
            float4 av[4], bv[6];
#pragma unroll
            for (int i = 0; i < 4; i++)
                av[i] = *((const float4*)(s_k + (gm * 4 + i) * 132 + h4 * 4));
#pragma unroll
            for (int j = 0; j < 6; j++)
                bv[j] = *((const float4*)(s_w + (gn + 32 * j) * 132 + h4 * 4));
#pragma unroll
            for (int i = 0; i < 4; i++)
#pragma unroll
                for (int j = 0; j < 6; j++) fma4(accA[i][j], av[i], bv[j]);
        }
    }

    // reduce per-row stats across the 8 partial threads per row
    s_s1[tid] = rs;
    s_s2[tid] = rs2;
    __syncthreads();
    if (tid < MTILE) {
        float a = 0.f, b2 = 0.f;
        for (int l = 0; l < 8; l++) { a += s_s1[tid + 32 * l]; b2 += s_s2[tid + 32 * l]; }
        float mu = a * (1.f / HIDD);
        float var = b2 * (1.f / HIDD) - mu * mu;
        s_mu[tid] = mu;
        s_sg[tid] = rsqrtf(var + 1e-5f);
    }

    // ---- GEMM3: r = xr @ Wr^T (two 96-row halves staged in s_w) ----
    float acc3[4][6];
#pragma unroll
    for (int i = 0; i < 4; i++)
#pragma unroll
        for (int j = 0; j < 6; j++) acc3[i][j] = 0.f;

    for (int half = 0; half < 2; half++) {
        __syncthreads();
        for (int i = tid; i < 96 * C4; i += 256) {
            int dd = i / C4, c4 = i % C4;
            *((float4*)(s_w + dd * 196 + c4 * 4)) =
                ((const float4*)(Wr + (size_t)(half * 96 + dd) * Cc))[c4];
        }
        __syncthreads();
#pragma unroll 2
        for (int c4 = 0; c4 < C4; c4++) {
            float4 av[4], bv[3];
#pragma unroll
            for (int i = 0; i < 4; i++)
                av[i] = *((const float4*)(s_xr + (gm * 4 + i) * 196 + c4 * 4));
#pragma unroll
            for (int jj = 0; jj < 3; jj++)
                bv[jj] = *((const float4*)(s_w + (gn + 32 * jj) * 196 + c4 * 4));
#pragma unroll
            for (int i = 0; i < 4; i++)
#pragma unroll
                for (int jj = 0; jj < 3; jj++) fma4(acc3[i][3 * half + jj], av[i], bv[jj]);
        }
    }

    // ---- epilogue: kv = s*(A - mu*G) + Bc ; out = sigmoid(r) * kv ----
#pragma unroll
    for (int i = 0; i < 4; i++) {
        int m = gm * 4 + i;
        float mu = s_mu[m], sg = s_sg[m];
#pragma unroll
        for (int j = 0; j < 6; j++) {
            int c = gn + 32 * j;
            float kv = sg * (accA[i][j] - mu * s_G[c]) + s_B[c];
            float r = 1.f / (1.f + expf(-acc3[i][j]));
            out[(m0 + m) * Cc + c] = r * kv;
        }
    }
}

// ---------------- host launcher ----------------
extern "C" void kernel_launch(void* const* d_in, const int* in_sizes, int n_in,
                              void* d_out, int out_size) {
    const float* x     = (const float*)d_in[0];
    const float* w1    = (const float*)d_in[1];
    const float* w3    = (const float*)d_in[2];
    const float* w5    = (const float*)d_in[3];
    const float* alpha = (const float*)d_in[4];
    const float* mixk  = (const float*)d_in[5];
    const float* mixr  = (const float*)d_in[6];
    const float* Wk    = (const float*)d_in[7];
    const float* ln_g  = (const float*)d_in[8];
    const float* ln_b  = (const float*)d_in[9];
    const float* Wr    = (const float*)d_in[10];
    const float* Wv    = (const float*)d_in[11];
    float* out = (float*)d_out;

    int nrow = in_sizes[0] / Cc;     // B*T
    int Bv = nrow / Tt;              // batch

    prep_eff<<<1, 192>>>(w1, w3, w5, alpha);
    prep_wv<<<(Cc * HIDD + 255) / 256, 256>>>(Wv, ln_g);
    prep_gb<<<1, 192>>>(Wv, ln_g, ln_b);
    conv_k<<<dim3(Ww / 32, Hh, Bv), 192>>>(x);

    cudaFuncSetAttribute(fused, cudaFuncAttributeMaxDynamicSharedMemorySize, SMEM_BYTES);
    fused<<<nrow / MTILE, 256, SMEM_BYTES>>>(x, mixk, mixr, Wk, Wr, out);
}

// round 5
// speedup vs baseline: 2.4808x; 2.4790x over previous
#include <cuda_runtime.h>
#include <cuda_bf16.h>
#include <cstdint>
#include <math.h>

#define Bmax  8
#define Hh    128
#define Ww    128
#define Tt    (Hh*Ww)
#define Cc    192
#define C4    48
#define HIDD  768
#define NROWMAX ((size_t)Bmax * Tt)

// ---------------- SMEM layout (bytes) ----------------
#define STRA 400                 // row stride for K=192 tiles (192*2 + 16)
#define STRK 272                 // row stride for K=128 tiles (128*2 + 16)
#define SA_H 0                   // A hi plane  [128 x 192]
#define SA_L 51200               // A lo plane
#define SB   102400              // B plane region (max 52,224)
#define SR3  154624              // region3: GEMM3 B plane (76,800) or k hi/lo
#define SK_H SR3                 // k-chunk hi [128 x 128], 34,816
#define SK_L (SR3 + 34816)       // k-chunk lo
#define SMEM_TOTAL 231424

// ---------------- mma / ldmatrix helpers ----------------
#define LDSM4(r0, r1, r2, r3, addr) \
    asm volatile("ldmatrix.sync.aligned.m8n8.x4.shared.b16 {%0,%1,%2,%3}, [%4];" \
                 : "=r"(r0), "=r"(r1), "=r"(r2), "=r"(r3) : "r"(addr))

__device__ __forceinline__ void mma16816(float* c, uint32_t a0, uint32_t a1, uint32_t a2,
                                         uint32_t a3, uint32_t b0, uint32_t b1) {
    asm volatile(
        "mma.sync.aligned.m16n8k16.row.col.f32.bf16.bf16.f32 "
        "{%0,%1,%2,%3}, {%4,%5,%6,%7}, {%8,%9}, {%0,%1,%2,%3};"
        : "+f"(c[0]), "+f"(c[1]), "+f"(c[2]), "+f"(c[3])
        : "r"(a0), "r"(a1), "r"(a2), "r"(a3), "r"(b0), "r"(b1));
}

__device__ __forceinline__ uint32_t smem_to_u32(const void* p) {
    uint32_t a;
    asm("{ .reg .u64 t; cvta.to.shared.u64 t, %1; cvt.u32.u64 %0, t; }" : "=r"(a) : "l"(p));
    return a;
}

__device__ __forceinline__ void split2(float v, unsigned short& h, unsigned short& l) {
    __nv_bfloat16 hb = __float2bfloat16(v);
    float r = v - __bfloat162float(hb);
    h = __bfloat16_as_ushort(hb);
    l = __bfloat16_as_ushort(__float2bfloat16(r));
}

// Warp-level pass: acc[2][NT][4] += A[32 x 16*ks] @ B^T.  A rows at aBase (warp's m
// offset folded in), B n-rows at bBase (warp's n offset folded in). Strides in bytes.
template <int NT>
__device__ __forceinline__ void wpass(float* acc, uint32_t aBase, uint32_t bBase,
                                      int sA, int sB, int ksteps, int lane) {
    uint32_t aAddr = aBase + (uint32_t)(lane & 15) * sA + ((lane & 16) ? 16u : 0u);
    uint32_t bAddr = bBase + (uint32_t)((lane & 7) + ((lane & 16) >> 1)) * sB
                     + ((lane & 8) ? 16u : 0u);
#pragma unroll 2
    for (int ks = 0; ks < ksteps; ks++) {
        uint32_t a[8];
        LDSM4(a[0], a[1], a[2], a[3], aAddr + ks * 32);
        LDSM4(a[4], a[5], a[6], a[7], aAddr + ks * 32 + 16 * sA);
#pragma unroll
        for (int p = 0; p < NT / 2; p++) {
            uint32_t b0, b1, b2, b3;
            LDSM4(b0, b1, b2, b3, bAddr + ks * 32 + p * 16 * sB);
            mma16816(acc + (0 * NT + 2 * p) * 4, a[0], a[1], a[2], a[3], b0, b1);
            mma16816(acc + (0 * NT + 2 * p + 1) * 4, a[0], a[1], a[2], a[3], b2, b3);
            mma16816(acc + (1 * NT + 2 * p) * 4, a[4], a[5], a[6], a[7], b0, b1);
            mma16816(acc + (1 * NT + 2 * p + 1) * 4, a[4], a[5], a[6], a[7], b2, b3);
        }
    }
}

// ---------------- scratch globals ----------------
__device__ float4 g_xx[NROWMAX * C4];
__device__ float  g_r[NROWMAX * Cc];
__device__ float  g_eff[Cc * 25];
__device__ float  g_G[Cc];
__device__ float  g_Bc[Cc];
__device__ __align__(16) __nv_bfloat16 g_wk_hi[HIDD * Cc], g_wk_lo[HIDD * Cc];
__device__ __align__(16) __nv_bfloat16 g_wr_hi[Cc * Cc],  g_wr_lo[Cc * Cc];
__device__ __align__(16) __nv_bfloat16 g_wvp_hi[Cc * HIDD], g_wvp_lo[Cc * HIDD];

// ---------------- prep kernels ----------------
__global__ void prep_eff(const float* __restrict__ w1, const float* __restrict__ w3,
                         const float* __restrict__ w5, const float* __restrict__ alpha) {
    int c = threadIdx.x;
    float a0 = alpha[0], a1 = alpha[1], a2 = alpha[2], a3 = alpha[3];
    for (int t = 0; t < 25; t++) {
        int di = t / 5, dj = t % 5;
        float v = a3 * w5[c * 25 + t];
        if (di >= 1 && di <= 3 && dj >= 1 && dj <= 3)
            v += a2 * w3[c * 9 + (di - 1) * 3 + (dj - 1)];
        if (di == 2 && dj == 2) v += a1 * w1[c] + a0;
        g_eff[c * 25 + t] = v;
    }
}
__global__ void prep_gb(const float* __restrict__ Wv, const float* __restrict__ g,
                        const float* __restrict__ bb) {
    int c = threadIdx.x;
    float sg = 0.f, sb = 0.f;
    for (int h = 0; h < HIDD; h++) {
        float w = Wv[(size_t)c * HIDD + h];
        sg += g[h] * w;
        sb += bb[h] * w;
    }
    g_G[c] = sg;
    g_Bc[c] = sb;
}
__global__ void prep_split(const float* __restrict__ src, __nv_bfloat16* dst_hi,
                           __nv_bfloat16* dst_lo, int n) {
    int i = blockIdx.x * 256 + threadIdx.x;
    if (i < n) {
        unsigned short h, l;
        split2(src[i], h, l);
        dst_hi[i] = __ushort_as_bfloat16(h);
        dst_lo[i] = __ushort_as_bfloat16(l);
    }
}
__global__ void prep_wvp(const float* __restrict__ Wv, const float* __restrict__ g, int n) {
    int i = blockIdx.x * 256 + threadIdx.x;
    if (i < n) {
        float v = Wv[i] * g[i % HIDD];
        unsigned short h, l;
        split2(v, h, l);
        g_wvp_hi[i] = __ushort_as_bfloat16(h);
        g_wvp_lo[i] = __ushort_as_bfloat16(l);
    }
}

// ---------------- OmniShift conv kernel (validated R1) ----------------
__global__ void __launch_bounds__(192) conv_k(const float* __restrict__ x) {
    __shared__ float4 s_eff[25][48];
    int tid = threadIdx.x;
    for (int i = tid; i < 25 * 48; i += 192) {
        int tap = i / 48, c4 = i % 48;
        int c = c4 * 4;
        s_eff[tap][c4] = make_float4(g_eff[(c + 0) * 25 + tap], g_eff[(c + 1) * 25 + tap],
                                     g_eff[(c + 2) * 25 + tap], g_eff[(c + 3) * 25 + tap]);
    }
    __syncthreads();
    int c4 = tid % 48, wseg = tid / 48;
    int w0 = (blockIdx.x * 4 + wseg) * 8;
    int h = blockIdx.y;
    size_t bbase = (size_t)blockIdx.z * Tt * C4;
    const float4* xb = ((const float4*)x) + bbase;
    float4 acc[8];
#pragma unroll
    for (int k = 0; k < 8; k++) acc[k] = make_float4(0.f, 0.f, 0.f, 0.f);
#pragma unroll
    for (int di = -2; di <= 2; di++) {
        int hh = h + di;
        float4 row[12];
        if (hh >= 0 && hh < Hh) {
            const float4* xr = xb + (size_t)hh * Ww * C4 + c4;
#pragma unroll
            for (int j = 0; j < 12; j++) {
                int w = w0 - 2 + j;
                row[j] = (w >= 0 && w < Ww) ? xr[(size_t)w * C4] : make_float4(0.f, 0.f, 0.f, 0.f);
            }
        } else {
#pragma unroll
            for (int j = 0; j < 12; j++) row[j] = make_float4(0.f, 0.f, 0.f, 0.f);
        }
#pragma unroll
        for (int dj = 0; dj < 5; dj++) {
            float4 wg = s_eff[(di + 2) * 5 + dj][c4];
#pragma unroll
            for (int k = 0; k < 8; k++) {
                acc[k].x = fmaf(row[k + dj].x, wg.x, acc[k].x);
                acc[k].y = fmaf(row[k + dj].y, wg.y, acc[k].y);
                acc[k].z = fmaf(row[k + dj].z, wg.z, acc[k].z);
                acc[k].w = fmaf(row[k + dj].w, wg.w, acc[k].w);
            }
        }
    }
    float4* xxb = g_xx + bbase + (size_t)h * Ww * C4 + c4;
#pragma unroll
    for (int k = 0; k < 8; k++) xxb[(size_t)(w0 + k) * C4] = acc[k];
}

// ---------------- staging helpers ----------------
__device__ __forceinline__ void stage_Axy(char* smem, const float* __restrict__ x,
                                          const float* __restrict__ mix, size_t m0, int tid) {
    for (int i = tid; i < 128 * 48; i += 256) {
        int r = i / 48, c4 = i - r * 48;
        float4 xv = ((const float4*)x)[(m0 + r) * 48 + c4];
        float4 xxv = g_xx[(m0 + r) * 48 + c4];
        float4 mk = ((const float4*)mix)[c4];
        float v0 = xv.x * mk.x + xxv.x * (1.f - mk.x);
        float v1 = xv.y * mk.y + xxv.y * (1.f - mk.y);
        float v2 = xv.z * mk.z + xxv.z * (1.f - mk.z);
        float v3 = xv.w * mk.w + xxv.w * (1.f - mk.w);
        unsigned short h0, h1, h2, h3, l0, l1, l2, l3;
        split2(v0, h0, l0); split2(v1, h1, l1); split2(v2, h2, l2); split2(v3, h3, l3);
        uint32_t off = (uint32_t)r * STRA + c4 * 8;
        *(uint2*)(smem + SA_H + off) =
            make_uint2((uint32_t)h0 | ((uint32_t)h1 << 16), (uint32_t)h2 | ((uint32_t)h3 << 16));
        *(uint2*)(smem + SA_L + off) =
            make_uint2((uint32_t)l0 | ((uint32_t)l1 << 16), (uint32_t)l2 | ((uint32_t)l3 << 16));
    }
}
// copy [rows x kcols] bf16 (row stride srcStride elems) -> smem dstOff with dstStride bytes
template <int PER>   // PER = kcols/8
__device__ __forceinline__ void stage_w(char* smem, uint32_t dstOff,
                                        const __nv_bfloat16* __restrict__ src, int rows,
                                        int srcStride, int dstStride, int tid) {
    int n = rows * PER;
    for (int i = tid; i < n; i += 256) {
        int r = i / PER, q = i - r * PER;
        uint4 v = *(const uint4*)(src + (size_t)r * srcStride + q * 8);
        *(uint4*)(smem + dstOff + (uint32_t)r * dstStride + q * 16) = v;
    }
}

// ---------------- fused tensor-core kernel ----------------
__global__ void __launch_bounds__(256, 1) fused_tc(
    const float* __restrict__ x, const float* __restrict__ mixk,
    const float* __restrict__ mixr, float* __restrict__ out)
{
    extern __shared__ char smem[];
    uint32_t sbase = smem_to_u32(smem);
    int tid = threadIdx.x, lane = tid & 31, wid = tid >> 5;
    int g = lane >> 2, tig = lane & 3;
    size_t m0 = (size_t)blockIdx.x * 128;
    int mw = (wid & 3) * 32;
    int nw12 = (wid >> 2) * 96;
    int nw8 = (wid >> 2) * 64;

    // ---------- Phase 1: GEMM3  r = sigmoid(xr @ Wr^T) ----------
    stage_Axy(smem, x, mixr, m0, tid);
    stage_w<24>(smem, SR3, g_wr_hi, 192, Cc, STRA, tid);
    __syncthreads();
    float acc3[96];
#pragma unroll
    for (int i = 0; i < 96; i++) acc3[i] = 0.f;
    wpass<12>(acc3, sbase + SA_H + mw * STRA, sbase + SR3 + nw12 * STRA, STRA, STRA, 12, lane);
    wpass<12>(acc3, sbase + SA_L + mw * STRA, sbase + SR3 + nw12 * STRA, STRA, STRA, 12, lane);
    __syncthreads();
    stage_w<24>(smem, SR3, g_wr_lo, 192, Cc, STRA, tid);
    __syncthreads();
    wpass<12>(acc3, sbase + SA_H + mw * STRA, sbase + SR3 + nw12 * STRA, STRA, STRA, 12, lane);
    {
        float* rdst = g_r + ((size_t)blockIdx.x * 8 + wid) * 96 * 32 + lane;
#pragma unroll
        for (int v = 0; v < 96; v++) rdst[(size_t)v * 32] = 1.f / (1.f + expf(-acc3[v]));
    }
    __syncthreads();

    // ---------- Phase 2: restage A with mix_k ----------
    stage_Axy(smem, x, mixk, m0, tid);

    float accA[96];
#pragma unroll
    for (int i = 0; i < 96; i++) accA[i] = 0.f;
    float rs[4] = {0.f, 0.f, 0.f, 0.f}, rq[4] = {0.f, 0.f, 0.f, 0.f};

    for (int ht = 0; ht < 6; ht++) {
        __syncthreads();
        stage_w<24>(smem, SB, g_wk_hi + (size_t)ht * 128 * Cc, 128, Cc, STRA, tid);
        __syncthreads();
        float acc1[64];
#pragma unroll
        for (int i = 0; i < 64; i++) acc1[i] = 0.f;
        wpass<8>(acc1, sbase + SA_H + mw * STRA, sbase + SB + nw8 * STRA, STRA, STRA, 12, lane);
        wpass<8>(acc1, sbase + SA_L + mw * STRA, sbase + SB + nw8 * STRA, STRA, STRA, 12, lane);
        __syncthreads();
        stage_w<24>(smem, SB, g_wk_lo + (size_t)ht * 128 * Cc, 128, Cc, STRA, tid);
        __syncthreads();
        wpass<8>(acc1, sbase + SA_H + mw * STRA, sbase + SB + nw8 * STRA, STRA, STRA, 12, lane);

        // relu^2 + stats + split write to k-chunk smem
#pragma unroll
        for (int mf = 0; mf < 2; mf++)
#pragma unroll
            for (int h8 = 0; h8 < 2; h8++) {
                int row = mw + mf * 16 + g + h8 * 8;
                int slot = mf * 2 + h8;
#pragma unroll
                for (int nt = 0; nt < 8; nt++) {
                    float v0 = acc1[(mf * 8 + nt) * 4 + h8 * 2 + 0];
                    float v1 = acc1[(mf * 8 + nt) * 4 + h8 * 2 + 1];
                    v0 = fmaxf(v0, 0.f); v0 *= v0;
                    v1 = fmaxf(v1, 0.f); v1 *= v1;
                    rs[slot] += v0 + v1;
                    rq[slot] += v0 * v0 + v1 * v1;
                    unsigned short h0, l0, h1, l1;
                    split2(v0, h0, l0);
                    split2(v1, h1, l1);
                    int col = nw8 + nt * 8 + 2 * tig;
                    uint32_t off = (uint32_t)row * STRK + col * 2;
                    *(uint32_t*)(smem + SK_H + off) = (uint32_t)h0 | ((uint32_t)h1 << 16);
                    *(uint32_t*)(smem + SK_L + off) = (uint32_t)l0 | ((uint32_t)l1 << 16);
                }
            }
        __syncthreads();
        stage_w<16>(smem, SB, g_wvp_hi + ht * 128, 192, HIDD, STRK, tid);
        __syncthreads();
        wpass<12>(accA, sbase + SK_H + mw * STRK, sbase + SB + nw12 * STRK, STRK, STRK, 8, lane);
        wpass<12>(accA, sbase + SK_L + mw * STRK, sbase + SB + nw12 * STRK, STRK, STRK, 8, lane);
        __syncthreads();
        stage_w<16>(smem, SB, g_wvp_lo + ht * 128, 192, HIDD, STRK, tid);
        __syncthreads();
        wpass<12>(accA, sbase + SK_H + mw * STRK, sbase + SB + nw12 * STRK, STRK, STRK, 8, lane);
    }
    __syncthreads();

    // ---------- stats reduce ----------
    float* s_sum  = (float*)(smem + SB);
    float* s_sum2 = (float*)(smem + SB + 512);
    float* s_mu   = (float*)(smem + SB + 1024);
    float* s_rstd = (float*)(smem + SB + 1536);
    float* s_G    = (float*)(smem + SB + 2048);
    float* s_Bv   = (float*)(smem + SB + 2816);
    if (tid < 128) { s_sum[tid] = 0.f; s_sum2[tid] = 0.f; }
    if (tid < 192) { s_G[tid] = g_G[tid]; s_Bv[tid] = g_Bc[tid]; }
    __syncthreads();
#pragma unroll
    for (int s = 0; s < 4; s++) {
        float a = rs[s], b = rq[s];
        a += __shfl_xor_sync(0xFFFFFFFFu, a, 1);
        a += __shfl_xor_sync(0xFFFFFFFFu, a, 2);
        b += __shfl_xor_sync(0xFFFFFFFFu, b, 1);
        b += __shfl_xor_sync(0xFFFFFFFFu, b, 2);
        if (tig == 0) {
            int row = mw + (s >> 1) * 16 + g + (s & 1) * 8;
            atomicAdd(&s_sum[row], a);
            atomicAdd(&s_sum2[row], b);
        }
    }
    __syncthreads();
    if (tid < 128) {
        float mu = s_sum[tid] * (1.f / HIDD);
        float var = s_sum2[tid] * (1.f / HIDD) - mu * mu;
        s_mu[tid] = mu;
        s_rstd[tid] = rsqrtf(var + 1e-5f);
    }
    __syncthreads();

    // ---------- epilogue ----------
    const float* rsrc = g_r + ((size_t)blockIdx.x * 8 + wid) * 96 * 32 + lane;
#pragma unroll
    for (int mf = 0; mf < 2; mf++)
#pragma unroll
        for (int h8 = 0; h8 < 2; h8++) {
            int row = mw + mf * 16 + g + h8 * 8;
            float mu = s_mu[row], rstd = s_rstd[row];
#pragma unroll
            for (int nt = 0; nt < 12; nt++) {
                int col = nw12 + nt * 8 + 2 * tig;
                int idx = (mf * 12 + nt) * 4 + h8 * 2;
                float kv0 = rstd * (accA[idx + 0] - mu * s_G[col + 0]) + s_Bv[col + 0];
                float kv1 = rstd * (accA[idx + 1] - mu * s_G[col + 1]) + s_Bv[col + 1];
                float r0 = rsrc[(size_t)(idx + 0) * 32];
                float r1 = rsrc[(size_t)(idx + 1) * 32];
                *(float2*)(out + (m0 + row) * Cc + col) = make_float2(r0 * kv0, r1 * kv1);
            }
        }
}

// ---------------- host launcher ----------------
extern "C" void kernel_launch(void* const* d_in, const int* in_sizes, int n_in,
                              void* d_out, int out_size) {
    const float* x     = (const float*)d_in[0];
    const float* w1    = (const float*)d_in[1];
    const float* w3    = (const float*)d_in[2];
    const float* w5    = (const float*)d_in[3];
    const float* alpha = (const float*)d_in[4];
    const float* mixk  = (const float*)d_in[5];
    const float* mixr  = (const float*)d_in[6];
    const float* Wk    = (const float*)d_in[7];
    const float* ln_g  = (const float*)d_in[8];
    const float* ln_b  = (const float*)d_in[9];
    const float* Wr    = (const float*)d_in[10];
    const float* Wv    = (const float*)d_in[11];
    float* out = (float*)d_out;

    int nrow = in_sizes[0] / Cc;
    int Bv = nrow / Tt;

    __nv_bfloat16 *wk_hi, *wk_lo, *wr_hi, *wr_lo;
    cudaGetSymbolAddress((void**)&wk_hi, g_wk_hi);
    cudaGetSymbolAddress((void**)&wk_lo, g_wk_lo);
    cudaGetSymbolAddress((void**)&wr_hi, g_wr_hi);
    cudaGetSymbolAddress((void**)&wr_lo, g_wr_lo);

    prep_eff<<<1, 192>>>(w1, w3, w5, alpha);
    prep_gb<<<1, 192>>>(Wv, ln_g, ln_b);
    prep_split<<<(HIDD * Cc + 255) / 256, 256>>>(Wk, wk_hi, wk_lo, HIDD * Cc);
    prep_split<<<(Cc * Cc + 255) / 256, 256>>>(Wr, wr_hi, wr_lo, Cc * Cc);
    prep_wvp<<<(Cc * HIDD + 255) / 256, 256>>>(Wv, ln_g, Cc * HIDD);
    conv_k<<<dim3(Ww / 32, Hh, Bv), 192>>>(x);

    cudaFuncSetAttribute(fused_tc, cudaFuncAttributeMaxDynamicSharedMemorySize, SMEM_TOTAL);
    fused_tc<<<nrow / 128, 256, SMEM_TOTAL>>>(x, mixk, mixr, out);
}